// round 1
// baseline (speedup 1.0000x reference)
#include <cuda_runtime.h>
#include <math.h>

// ---------------------------------------------------------------------------
// GRUEncoder: B=256, T=512, IN_DIM=75, H=256, 2-layer unidirectional GRU + FC
// Strategy:
//   K0: xg0 = x @ W_ih0^T + b_ih0            (batched GEMM, [B*T,768])
//   K1: layer0 recurrence (64 blocks x 4 batch rows, f32x2 FMA) -> out0
//   K2: xg1 = out0 @ W_ih1^T + b_ih1         (batched GEMM, reuse xg buffer)
//   K3: layer1 recurrence -> hT only
//   K4: emb = hT @ fc_W^T + fc_b -> d_out
// All fp32 (precision-safe), packed fma.rn.f32x2 for 2x fp32 FMA rate.
// ---------------------------------------------------------------------------

#define B_  256
#define T_  512
#define H_  256
#define G3_ 768
#define INDIM_ 75

// scratch (static device allocations; no cudaMalloc allowed)
__device__ float g_xg[(size_t)B_ * T_ * G3_];      // 402 MB, reused for xg0 and xg1
__device__ float g_out0[(size_t)B_ * T_ * H_];     // 134 MB
__device__ float g_hT[(size_t)B_ * H_];            // final hidden of layer 1

typedef unsigned long long u64;

__device__ __forceinline__ u64 pack2(float lo, float hi) {
    u64 d; asm("mov.b64 %0, {%1, %2};" : "=l"(d) : "f"(lo), "f"(hi)); return d;
}
__device__ __forceinline__ void unpack2(u64 v, float& lo, float& hi) {
    asm("mov.b64 {%0, %1}, %2;" : "=f"(lo), "=f"(hi) : "l"(v));
}
__device__ __forceinline__ u64 ffma2(u64 a, u64 b, u64 c) {
    u64 d; asm("fma.rn.f32x2 %0, %1, %2, %3;" : "=l"(d) : "l"(a), "l"(b), "l"(c)); return d;
}
__device__ __forceinline__ float sigmoidf_(float x) { return 1.0f / (1.0f + expf(-x)); }

// ---------------------------------------------------------------------------
// Tiled GEMM: C[M,N] = A[M,K] @ B[N,K]^T + bias[N]
// BM=128, BN=64, BK=8, 256 threads, each thread: 8 rows x 4 cols via f32x2.
// M must be a multiple of 128, N a multiple of 64 (true for all our calls).
// ---------------------------------------------------------------------------
__global__ __launch_bounds__(256)
void gemm_bias_kernel(const float* __restrict__ A, const float* __restrict__ Bm,
                      const float* __restrict__ bias, float* __restrict__ C,
                      int M, int N, int K)
{
    __shared__ __align__(16) float As[8][132];  // pad 4: conflict-free stores, aligned f4 reads
    __shared__ __align__(16) float Bs[8][68];

    const int tx = threadIdx.x & 15;
    const int ty = threadIdx.x >> 4;
    const int m0 = blockIdx.y * 128;
    const int n0 = blockIdx.x * 64;

    u64 acc[4][4];
#pragma unroll
    for (int p = 0; p < 4; p++)
#pragma unroll
        for (int c = 0; c < 4; c++) acc[p][c] = 0ull;

    for (int k0 = 0; k0 < K; k0 += 8) {
        // load A tile: 128x8 = 1024 elems, 4 per thread (k fastest -> coalesced groups)
#pragma unroll
        for (int i = 0; i < 4; i++) {
            int idx = threadIdx.x + i * 256;
            int m = idx >> 3, k = idx & 7;
            float v = 0.0f;
            if (k0 + k < K) v = A[(size_t)(m0 + m) * K + (k0 + k)];
            As[k][m] = v;
        }
        // load B tile: 64x8 = 512 elems, 2 per thread
#pragma unroll
        for (int i = 0; i < 2; i++) {
            int idx = threadIdx.x + i * 256;
            int n = idx >> 3, k = idx & 7;
            float v = 0.0f;
            if (k0 + k < K) v = Bm[(size_t)(n0 + n) * K + (k0 + k)];
            Bs[k][n] = v;
        }
        __syncthreads();

#pragma unroll
        for (int k = 0; k < 8; k++) {
            float4 a0 = *(const float4*)&As[k][ty * 8];
            float4 a1 = *(const float4*)&As[k][ty * 8 + 4];
            float4 b  = *(const float4*)&Bs[k][tx * 4];
            u64 ap[4] = { pack2(a0.x, a0.y), pack2(a0.z, a0.w),
                          pack2(a1.x, a1.y), pack2(a1.z, a1.w) };
            u64 bb[4] = { pack2(b.x, b.x), pack2(b.y, b.y),
                          pack2(b.z, b.z), pack2(b.w, b.w) };
#pragma unroll
            for (int p = 0; p < 4; p++)
#pragma unroll
                for (int c = 0; c < 4; c++)
                    acc[p][c] = ffma2(ap[p], bb[c], acc[p][c]);
        }
        __syncthreads();
    }

    float bv[4];
#pragma unroll
    for (int c = 0; c < 4; c++) bv[c] = bias[n0 + tx * 4 + c];

#pragma unroll
    for (int p = 0; p < 4; p++) {
        float lo[4], hi[4];
#pragma unroll
        for (int c = 0; c < 4; c++) unpack2(acc[p][c], lo[c], hi[c]);
        int r0 = m0 + ty * 8 + 2 * p;
        float4 o0 = make_float4(lo[0] + bv[0], lo[1] + bv[1], lo[2] + bv[2], lo[3] + bv[3]);
        float4 o1 = make_float4(hi[0] + bv[0], hi[1] + bv[1], hi[2] + bv[2], hi[3] + bv[3]);
        *(float4*)&C[(size_t)r0 * N + n0 + tx * 4]       = o0;
        *(float4*)&C[(size_t)(r0 + 1) * N + n0 + tx * 4] = o1;
    }
}

// ---------------------------------------------------------------------------
// GRU recurrence: 64 blocks x 256 threads; block owns 4 batch rows for all T.
// Thread j owns hidden unit j (all 4 rows). h kept in smem as sh[k][row] so a
// single broadcast float4 LDS yields the two packed row-pairs directly.
// Weights: W_hh[768][256] read per-thread-row contiguously as float4 (L2).
// xg already contains x@W_ih^T + b_ih.
// ---------------------------------------------------------------------------
template<bool WRITE_OUT, bool WRITE_HT>
__global__ __launch_bounds__(256)
void gru_layer_kernel(const float* __restrict__ xg, const float* __restrict__ Whh,
                      const float* __restrict__ bhh,
                      float* __restrict__ out, float* __restrict__ hT)
{
    __shared__ __align__(16) float sh[256][4];

    const int j  = threadIdx.x;
    const int r0 = blockIdx.x * 4;

    const float br = bhh[j], bz = bhh[256 + j], bn = bhh[512 + j];
    const float* Wr = Whh + (size_t)j * 256;
    const float* Wz = Whh + (size_t)(256 + j) * 256;
    const float* Wn = Whh + (size_t)(512 + j) * 256;

    float hreg[4] = {0.f, 0.f, 0.f, 0.f};
    *(float4*)&sh[j][0] = make_float4(0.f, 0.f, 0.f, 0.f);
    __syncthreads();

    for (int t = 0; t < T_; t++) {
        u64 accr0 = pack2(br, br), accr1 = accr0;
        u64 accz0 = pack2(bz, bz), accz1 = accz0;
        u64 accn0 = pack2(bn, bn), accn1 = accn0;

#pragma unroll 4
        for (int k = 0; k < 256; k += 4) {
            float4 wr = *(const float4*)(Wr + k);
            float4 wz = *(const float4*)(Wz + k);
            float4 wn = *(const float4*)(Wn + k);
            float4 h0 = *(const float4*)&sh[k][0];
            float4 h1 = *(const float4*)&sh[k + 1][0];
            float4 h2 = *(const float4*)&sh[k + 2][0];
            float4 h3 = *(const float4*)&sh[k + 3][0];

#define STEPK(hv, comp)                                                          \
            {                                                                    \
                u64 p01 = pack2(hv.x, hv.y), p23 = pack2(hv.z, hv.w);            \
                u64 w2;                                                          \
                w2 = pack2(wr.comp, wr.comp);                                    \
                accr0 = ffma2(p01, w2, accr0); accr1 = ffma2(p23, w2, accr1);    \
                w2 = pack2(wz.comp, wz.comp);                                    \
                accz0 = ffma2(p01, w2, accz0); accz1 = ffma2(p23, w2, accz1);    \
                w2 = pack2(wn.comp, wn.comp);                                    \
                accn0 = ffma2(p01, w2, accn0); accn1 = ffma2(p23, w2, accn1);    \
            }
            STEPK(h0, x) STEPK(h1, y) STEPK(h2, z) STEPK(h3, w)
#undef STEPK
        }

        float hr[4], hz[4], hn[4];
        unpack2(accr0, hr[0], hr[1]); unpack2(accr1, hr[2], hr[3]);
        unpack2(accz0, hz[0], hz[1]); unpack2(accz1, hz[2], hz[3]);
        unpack2(accn0, hn[0], hn[1]); unpack2(accn1, hn[2], hn[3]);

        __syncthreads();  // all reads of sh for step t complete

        float hnew[4];
#pragma unroll
        for (int row = 0; row < 4; row++) {
            size_t base = ((size_t)(r0 + row) * T_ + t) * G3_ + j;
            float xr = xg[base], xz = xg[base + 256], xn = xg[base + 512];
            float r = sigmoidf_(xr + hr[row]);
            float z = sigmoidf_(xz + hz[row]);
            float n = tanhf(xn + r * hn[row]);
            float h = (1.0f - z) * n + z * hreg[row];
            hreg[row] = h;
            hnew[row] = h;
            if (WRITE_OUT)
                out[((size_t)(r0 + row) * T_ + t) * H_ + j] = h;
        }
        *(float4*)&sh[j][0] = make_float4(hnew[0], hnew[1], hnew[2], hnew[3]);
        __syncthreads();  // sh update visible before next step's reads
    }

    if (WRITE_HT) {
#pragma unroll
        for (int row = 0; row < 4; row++)
            hT[(size_t)(r0 + row) * H_ + j] = hreg[row];
    }
}

// ---------------------------------------------------------------------------
extern "C" void kernel_launch(void* const* d_in, const int* in_sizes, int n_in,
                              void* d_out, int out_size)
{
    const float* x     = (const float*)d_in[0];   // [256,512,25,3] = [B*T, 75]
    const float* W_ih0 = (const float*)d_in[1];   // [768, 75]
    const float* W_hh0 = (const float*)d_in[2];   // [768, 256]
    const float* b_ih0 = (const float*)d_in[3];
    const float* b_hh0 = (const float*)d_in[4];
    const float* W_ih1 = (const float*)d_in[5];   // [768, 256]
    const float* W_hh1 = (const float*)d_in[6];
    const float* b_ih1 = (const float*)d_in[7];
    const float* b_hh1 = (const float*)d_in[8];
    const float* fc_W  = (const float*)d_in[9];   // [256, 256]
    const float* fc_b  = (const float*)d_in[10];
    float* out = (float*)d_out;

    float *xg, *out0, *hT;
    cudaGetSymbolAddress((void**)&xg,   g_xg);
    cudaGetSymbolAddress((void**)&out0, g_out0);
    cudaGetSymbolAddress((void**)&hT,   g_hT);

    const int MT = B_ * T_;  // 131072

    // K0: xg0 = x @ W_ih0^T + b_ih0
    gemm_bias_kernel<<<dim3(G3_ / 64, MT / 128), 256>>>(x, W_ih0, b_ih0, xg, MT, G3_, INDIM_);
    // K1: layer 0 recurrence -> out0
    gru_layer_kernel<true, false><<<64, 256>>>(xg, W_hh0, b_hh0, out0, nullptr);
    // K2: xg1 = out0 @ W_ih1^T + b_ih1  (reuse xg buffer)
    gemm_bias_kernel<<<dim3(G3_ / 64, MT / 128), 256>>>(out0, W_ih1, b_ih1, xg, MT, G3_, H_);
    // K3: layer 1 recurrence -> hT
    gru_layer_kernel<false, true><<<64, 256>>>(xg, W_hh1, b_hh1, nullptr, hT);
    // K4: embedding = hT @ fc_W^T + fc_b
    gemm_bias_kernel<<<dim3(H_ / 64, B_ / 128), 256>>>(hT, fc_W, fc_b, out, B_, H_, H_);
}

// round 2
// speedup vs baseline: 9.3680x; 9.3680x over previous
#include <cuda_runtime.h>
#include <math.h>
#include <stdint.h>

// ---------------------------------------------------------------------------
// GRUEncoder: B=256, T=512, IN_DIM=75, H=256, 2-layer GRU + FC
//   K0: xg0 = x @ W_ih0^T + b_ih0
//   K1: layer0 recurrence  (4-CTA clusters, W_hh in SMEM, DSMEM h-exchange)
//   K2: xg1 = out0 @ W_ih1^T + b_ih1
//   K3: layer1 recurrence -> hT
//   K4: emb = hT @ fc_W^T + fc_b
// ---------------------------------------------------------------------------

#define B_  256
#define T_  512
#define H_  256
#define G3_ 768
#define INDIM_ 75

__device__ float g_xg[(size_t)B_ * T_ * G3_];      // reused for xg0 and xg1
__device__ float g_out0[(size_t)B_ * T_ * H_];
__device__ float g_hT[(size_t)B_ * H_];

typedef unsigned long long u64;

__device__ __forceinline__ u64 pack2(float lo, float hi) {
    u64 d; asm("mov.b64 %0, {%1, %2};" : "=l"(d) : "f"(lo), "f"(hi)); return d;
}
__device__ __forceinline__ void unpack2(u64 v, float& lo, float& hi) {
    asm("mov.b64 {%0, %1}, %2;" : "=f"(lo), "=f"(hi) : "l"(v));
}
__device__ __forceinline__ u64 ffma2(u64 a, u64 b, u64 c) {
    u64 d; asm("fma.rn.f32x2 %0, %1, %2, %3;" : "=l"(d) : "l"(a), "l"(b), "l"(c)); return d;
}
__device__ __forceinline__ u64 add2(u64 a, u64 b) {
    u64 d; asm("add.rn.f32x2 %0, %1, %2;" : "=l"(d) : "l"(a), "l"(b)); return d;
}
__device__ __forceinline__ uint32_t smem_u32(const void* p) {
    uint32_t a;
    asm("{ .reg .u64 t; cvta.to.shared.u64 t, %1; cvt.u32.u64 %0, t; }" : "=r"(a) : "l"(p));
    return a;
}
__device__ __forceinline__ uint32_t mapa_(uint32_t addr, uint32_t rank) {
    uint32_t r; asm("mapa.shared::cluster.u32 %0, %1, %2;" : "=r"(r) : "r"(addr), "r"(rank));
    return r;
}
__device__ __forceinline__ void st_cluster_u64(uint32_t addr, u64 v) {
    asm volatile("st.shared::cluster.b64 [%0], %1;" :: "r"(addr), "l"(v) : "memory");
}
__device__ __forceinline__ uint32_t ctarank_() {
    uint32_t r; asm("mov.u32 %0, %%cluster_ctarank;" : "=r"(r)); return r;
}
#define CLUSTER_BAR() do { \
    asm volatile("barrier.cluster.arrive.aligned;" ::: "memory"); \
    asm volatile("barrier.cluster.wait.aligned;"   ::: "memory"); } while (0)

__device__ __forceinline__ float sigm(float x)  { return __fdividef(1.f, 1.f + __expf(-x)); }
__device__ __forceinline__ float tanhf_(float x){ return __fdividef(2.f, 1.f + __expf(-2.f * x)) - 1.f; }

// ---------------------------------------------------------------------------
// Tiled GEMM: C[M,N] = A[M,K] @ B[N,K]^T + bias[N]   (unchanged from R1)
// ---------------------------------------------------------------------------
__global__ __launch_bounds__(256)
void gemm_bias_kernel(const float* __restrict__ A, const float* __restrict__ Bm,
                      const float* __restrict__ bias, float* __restrict__ C,
                      int M, int N, int K)
{
    __shared__ __align__(16) float As[8][132];
    __shared__ __align__(16) float Bs[8][68];

    const int tx = threadIdx.x & 15;
    const int ty = threadIdx.x >> 4;
    const int m0 = blockIdx.y * 128;
    const int n0 = blockIdx.x * 64;

    u64 acc[4][4];
#pragma unroll
    for (int p = 0; p < 4; p++)
#pragma unroll
        for (int c = 0; c < 4; c++) acc[p][c] = 0ull;

    for (int k0 = 0; k0 < K; k0 += 8) {
#pragma unroll
        for (int i = 0; i < 4; i++) {
            int idx = threadIdx.x + i * 256;
            int m = idx >> 3, k = idx & 7;
            float v = 0.0f;
            if (k0 + k < K) v = A[(size_t)(m0 + m) * K + (k0 + k)];
            As[k][m] = v;
        }
#pragma unroll
        for (int i = 0; i < 2; i++) {
            int idx = threadIdx.x + i * 256;
            int n = idx >> 3, k = idx & 7;
            float v = 0.0f;
            if (k0 + k < K) v = Bm[(size_t)(n0 + n) * K + (k0 + k)];
            Bs[k][n] = v;
        }
        __syncthreads();

#pragma unroll
        for (int k = 0; k < 8; k++) {
            float4 a0 = *(const float4*)&As[k][ty * 8];
            float4 a1 = *(const float4*)&As[k][ty * 8 + 4];
            float4 b  = *(const float4*)&Bs[k][tx * 4];
            u64 ap[4] = { pack2(a0.x, a0.y), pack2(a0.z, a0.w),
                          pack2(a1.x, a1.y), pack2(a1.z, a1.w) };
            u64 bb[4] = { pack2(b.x, b.x), pack2(b.y, b.y),
                          pack2(b.z, b.z), pack2(b.w, b.w) };
#pragma unroll
            for (int p = 0; p < 4; p++)
#pragma unroll
                for (int c = 0; c < 4; c++)
                    acc[p][c] = ffma2(ap[p], bb[c], acc[p][c]);
        }
        __syncthreads();
    }

    float bv[4];
#pragma unroll
    for (int c = 0; c < 4; c++) bv[c] = bias[n0 + tx * 4 + c];

#pragma unroll
    for (int p = 0; p < 4; p++) {
        float lo[4], hi[4];
#pragma unroll
        for (int c = 0; c < 4; c++) unpack2(acc[p][c], lo[c], hi[c]);
        int r0 = m0 + ty * 8 + 2 * p;
        float4 o0 = make_float4(lo[0] + bv[0], lo[1] + bv[1], lo[2] + bv[2], lo[3] + bv[3]);
        float4 o1 = make_float4(hi[0] + bv[0], hi[1] + bv[1], hi[2] + bv[2], hi[3] + bv[3]);
        *(float4*)&C[(size_t)r0 * N + n0 + tx * 4]       = o0;
        *(float4*)&C[(size_t)(r0 + 1) * N + n0 + tx * 4] = o1;
    }
}

// ---------------------------------------------------------------------------
// Cluster GRU recurrence.
// Cluster of 4 CTAs handles 8 batch rows (32 clusters, 128 CTAs total).
// CTA rank c owns hidden units [c*64, c*64+64): its 192 gate rows of W_hh
// live in SMEM (192KB, k-major: Ws[k][g*64+u]).
// 256 threads = 4 k-slices (64 k each) x 64 units. Thread (u, s):
//   GEMM phase: accumulates r/z/n pre-acts for unit u over k in [64s,64s+64)
//               for all 8 rows (4 row-pair f32x2 accumulators per gate).
//   Finalize:   cross-slice reduce via SMEM, computes h_new for rows 2s,2s+1,
//               broadcasts packed row-pair to all 4 CTAs' h buffer via DSMEM.
// One cluster barrier per step; h double-buffered.
// SMEM: Ws 192KB | h[2][256][4] u64 16KB | red[4][3][3][64] u64 18KB = 226KB
// ---------------------------------------------------------------------------
#define WS_BYTES   196608
#define HBUF_OFF   WS_BYTES
#define RED_OFF    (WS_BYTES + 16384)
#define GRU_SMEM   (RED_OFF + 18432)        // 231424 <= 232448 (sm_103a max)

template<bool WRITE_OUT, bool WRITE_HT>
__global__ void __cluster_dims__(4, 1, 1) __launch_bounds__(256, 1)
gru_cluster_kernel(const float* __restrict__ xg, const float* __restrict__ Whh,
                   const float* __restrict__ bhh,
                   float* __restrict__ out, float* __restrict__ hT)
{
    extern __shared__ __align__(16) char smem[];
    float* Ws  = (float*)smem;                  // [256][192]
    u64*   hb  = (u64*)(smem + HBUF_OFF);       // [2][256][4] row-pairs
    u64*   red = (u64*)(smem + RED_OFF);        // [4][3][3][64]

    const int tid = threadIdx.x;
    const int u   = tid & 63;
    const int s   = tid >> 6;                   // k-slice / row-pair owner
    const uint32_t crank = ctarank_();          // 0..3
    const int cu  = (int)crank * 64 + u;        // global hidden unit
    const int cluster_id = blockIdx.x >> 2;
    const int row0 = cluster_id * 8;            // 8 batch rows per cluster

    // ---- stage this CTA's 192 W_hh rows into SMEM, k-major ----
    for (int idx = tid; idx < 192 * 64; idx += 256) {
        int o  = idx % 192;                     // output: g*64 + unit
        int kb = idx / 192;                     // k/4
        int g  = o >> 6, uo = o & 63;
        int grow = g * 256 + (int)crank * 64 + uo;
        float4 w = ((const float4*)Whh)[grow * 64 + kb];
        float* base = Ws + (kb * 4) * 192 + o;
        base[0] = w.x; base[192] = w.y; base[384] = w.z; base[576] = w.w;
    }
    // zero h buffer 0 (t=0 reads it)
    for (int idx = tid; idx < 1024; idx += 256) hb[idx] = 0ull;
    __syncthreads();
    CLUSTER_BAR();

    const float br = bhh[cu], bz = bhh[256 + cu], bn = bhh[512 + cu];

    // DSMEM addresses of this thread's h slot (parity 0) in each cluster CTA
    uint32_t hslot = smem_u32(&hb[(size_t)cu * 4 + s]);
    uint32_t maddr[4];
#pragma unroll
    for (int rk = 0; rk < 4; rk++) maddr[rk] = mapa_(hslot, (uint32_t)rk);

    // xg / out pointers for this thread's two rows
    const int r0g = row0 + 2 * s;
    const float* px0 = xg + ((size_t)r0g * T_) * G3_ + cu;
    const float* px1 = px0 + (size_t)T_ * G3_;
    float* po0 = WRITE_OUT ? out + ((size_t)r0g * T_) * H_ + cu : nullptr;
    float* po1 = WRITE_OUT ? po0 + (size_t)T_ * H_ : nullptr;

    float hp0 = 0.f, hp1 = 0.f;                 // h for rows 2s, 2s+1 of unit cu

    for (int t = 0; t < T_; t++) {
        // prefetch xg for this step (hidden under GEMM)
        float x_r0 = px0[0], x_z0 = px0[256], x_n0 = px0[512];
        float x_r1 = px1[0], x_z1 = px1[256], x_n1 = px1[512];

        const u64* cur = hb + (size_t)(t & 1) * 1024;

        u64 acc[3][4];
#pragma unroll
        for (int g = 0; g < 3; g++)
#pragma unroll
            for (int rp = 0; rp < 4; rp++) acc[g][rp] = 0ull;

        {
            const float* wsp = Ws + (size_t)(s * 64) * 192;
            const u64*   hk  = cur + (size_t)(s * 64) * 4;
#pragma unroll 4
            for (int k = 0; k < 64; k++) {
                float wr = wsp[u], wz = wsp[64 + u], wn = wsp[128 + u];
                ulonglong2 hA = *(const ulonglong2*)(hk);
                ulonglong2 hB = *(const ulonglong2*)(hk + 2);
                u64 wr2 = pack2(wr, wr), wz2 = pack2(wz, wz), wn2 = pack2(wn, wn);
                acc[0][0] = ffma2(hA.x, wr2, acc[0][0]);
                acc[0][1] = ffma2(hA.y, wr2, acc[0][1]);
                acc[0][2] = ffma2(hB.x, wr2, acc[0][2]);
                acc[0][3] = ffma2(hB.y, wr2, acc[0][3]);
                acc[1][0] = ffma2(hA.x, wz2, acc[1][0]);
                acc[1][1] = ffma2(hA.y, wz2, acc[1][1]);
                acc[1][2] = ffma2(hB.x, wz2, acc[1][2]);
                acc[1][3] = ffma2(hB.y, wz2, acc[1][3]);
                acc[2][0] = ffma2(hA.x, wn2, acc[2][0]);
                acc[2][1] = ffma2(hA.y, wn2, acc[2][1]);
                acc[2][2] = ffma2(hB.x, wn2, acc[2][2]);
                acc[2][3] = ffma2(hB.y, wn2, acc[2][3]);
                wsp += 192; hk += 4;
            }
        }

        // store partials for the 3 row-pairs other slices finalize
#pragma unroll
        for (int g = 0; g < 3; g++) {
#pragma unroll
            for (int rp = 0; rp < 4; rp++) {
                if (rp != s) {
                    int j = rp - (rp > s ? 1 : 0);
                    red[(((size_t)s * 3 + g) * 3 + j) * 64 + u] = acc[g][rp];
                }
            }
        }
        __syncthreads();

        // reduce row-pair s across the 4 slices (own partial from regs)
        u64 own[3];
#pragma unroll
        for (int g = 0; g < 3; g++) {
            u64 v = acc[g][0];
            if (s == 1) v = acc[g][1];
            if (s == 2) v = acc[g][2];
            if (s == 3) v = acc[g][3];
#pragma unroll
            for (int sp = 0; sp < 4; sp++) {
                if (sp != s) {
                    int j = s - (s > sp ? 1 : 0);
                    v = add2(v, red[(((size_t)sp * 3 + g) * 3 + j) * 64 + u]);
                }
            }
            own[g] = v;
        }

        float pr0, pr1, pz0, pz1, pn0, pn1;
        unpack2(own[0], pr0, pr1);
        unpack2(own[1], pz0, pz1);
        unpack2(own[2], pn0, pn1);
        pr0 += br; pr1 += br; pz0 += bz; pz1 += bz; pn0 += bn; pn1 += bn;

        float r0 = sigm(x_r0 + pr0);
        float z0 = sigm(x_z0 + pz0);
        float n0 = tanhf_(x_n0 + r0 * pn0);
        float h0 = n0 + z0 * (hp0 - n0);

        float r1 = sigm(x_r1 + pr1);
        float z1 = sigm(x_z1 + pz1);
        float n1 = tanhf_(x_n1 + r1 * pn1);
        float h1 = n1 + z1 * (hp1 - n1);

        if (WRITE_OUT) { po0[0] = h0; po1[0] = h1; po0 += H_; po1 += H_; }

        // broadcast new row-pair to all 4 CTAs' next h buffer
        u64 hv = pack2(h0, h1);
        uint32_t poff = (uint32_t)((t + 1) & 1) * 8192u;
#pragma unroll
        for (int rk = 0; rk < 4; rk++) st_cluster_u64(maddr[rk] + poff, hv);

        CLUSTER_BAR();   // release writes, acquire peers' writes

        hp0 = h0; hp1 = h1;
        px0 += G3_; px1 += G3_;
    }

    if (WRITE_HT) {
        hT[(size_t)r0g * H_ + cu]       = hp0;
        hT[(size_t)(r0g + 1) * H_ + cu] = hp1;
    }
}

// ---------------------------------------------------------------------------
extern "C" void kernel_launch(void* const* d_in, const int* in_sizes, int n_in,
                              void* d_out, int out_size)
{
    const float* x     = (const float*)d_in[0];
    const float* W_ih0 = (const float*)d_in[1];
    const float* W_hh0 = (const float*)d_in[2];
    const float* b_ih0 = (const float*)d_in[3];
    const float* b_hh0 = (const float*)d_in[4];
    const float* W_ih1 = (const float*)d_in[5];
    const float* W_hh1 = (const float*)d_in[6];
    const float* b_ih1 = (const float*)d_in[7];
    const float* b_hh1 = (const float*)d_in[8];
    const float* fc_W  = (const float*)d_in[9];
    const float* fc_b  = (const float*)d_in[10];
    float* out = (float*)d_out;

    float *xg, *out0, *hT;
    cudaGetSymbolAddress((void**)&xg,   g_xg);
    cudaGetSymbolAddress((void**)&out0, g_out0);
    cudaGetSymbolAddress((void**)&hT,   g_hT);

    static int smem_set = 0;
    if (!smem_set) {
        cudaFuncSetAttribute(gru_cluster_kernel<true,  false>,
                             cudaFuncAttributeMaxDynamicSharedMemorySize, GRU_SMEM);
        cudaFuncSetAttribute(gru_cluster_kernel<false, true>,
                             cudaFuncAttributeMaxDynamicSharedMemorySize, GRU_SMEM);
        smem_set = 1;
    }

    const int MT = B_ * T_;

    gemm_bias_kernel<<<dim3(G3_ / 64, MT / 128), 256>>>(x, W_ih0, b_ih0, xg, MT, G3_, INDIM_);
    gru_cluster_kernel<true,  false><<<128, 256, GRU_SMEM>>>(xg, W_hh0, b_hh0, out0, nullptr);
    gemm_bias_kernel<<<dim3(G3_ / 64, MT / 128), 256>>>(out0, W_ih1, b_ih1, xg, MT, G3_, H_);
    gru_cluster_kernel<false, true><<<128, 256, GRU_SMEM>>>(xg, W_hh1, b_hh1, nullptr, hT);
    gemm_bias_kernel<<<dim3(H_ / 64, B_ / 128), 256>>>(hT, fc_W, fc_b, out, B_, H_, H_);
}

// round 5
// speedup vs baseline: 9.9076x; 1.0576x over previous
#include <cuda_runtime.h>
#include <math.h>
#include <stdint.h>

// ---------------------------------------------------------------------------
// GRUEncoder: B=256, T=512, IN_DIM=75, H=256, 2-layer GRU + FC
//   K0: xg0 = x @ W_ih0^T + b_ih0
//   K1: layer0 recurrence (4-CTA clusters, 2 pipelined row-groups, st.async)
//   K2: xg1 = out0 @ W_ih1^T + b_ih1
//   K3: layer1 recurrence -> hT
//   K4: emb = hT @ fc_W^T + fc_b
// ---------------------------------------------------------------------------

#define B_  256
#define T_  512
#define H_  256
#define G3_ 768
#define INDIM_ 75

__device__ float g_xg[(size_t)B_ * T_ * G3_];
__device__ float g_out0[(size_t)B_ * T_ * H_];
__device__ float g_hT[(size_t)B_ * H_];

typedef unsigned long long u64;

__device__ __forceinline__ u64 pack2(float lo, float hi) {
    u64 d; asm("mov.b64 %0, {%1, %2};" : "=l"(d) : "f"(lo), "f"(hi)); return d;
}
__device__ __forceinline__ void unpack2(u64 v, float& lo, float& hi) {
    asm("mov.b64 {%0, %1}, %2;" : "=f"(lo), "=f"(hi) : "l"(v));
}
__device__ __forceinline__ u64 ffma2(u64 a, u64 b, u64 c) {
    u64 d; asm("fma.rn.f32x2 %0, %1, %2, %3;" : "=l"(d) : "l"(a), "l"(b), "l"(c)); return d;
}
__device__ __forceinline__ u64 add2(u64 a, u64 b) {
    u64 d; asm("add.rn.f32x2 %0, %1, %2;" : "=l"(d) : "l"(a), "l"(b)); return d;
}
__device__ __forceinline__ uint32_t smem_u32(const void* p) {
    uint32_t a;
    asm("{ .reg .u64 t; cvta.to.shared.u64 t, %1; cvt.u32.u64 %0, t; }" : "=r"(a) : "l"(p));
    return a;
}
__device__ __forceinline__ uint32_t mapa_(uint32_t addr, uint32_t rank) {
    uint32_t r; asm("mapa.shared::cluster.u32 %0, %1, %2;" : "=r"(r) : "r"(addr), "r"(rank));
    return r;
}
__device__ __forceinline__ uint32_t ctarank_() {
    uint32_t r; asm("mov.u32 %0, %%cluster_ctarank;" : "=r"(r)); return r;
}
#define CLUSTER_BAR() do { \
    asm volatile("barrier.cluster.arrive.aligned;" ::: "memory"); \
    asm volatile("barrier.cluster.wait.aligned;"   ::: "memory"); } while (0)

__device__ __forceinline__ void mbar_init(uint32_t addr, uint32_t cnt) {
    asm volatile("mbarrier.init.shared.b64 [%0], %1;" :: "r"(addr), "r"(cnt) : "memory");
}
__device__ __forceinline__ void mbar_expect_tx(uint32_t addr, uint32_t bytes) {
    asm volatile("mbarrier.arrive.expect_tx.shared.b64 _, [%0], %1;"
                 :: "r"(addr), "r"(bytes) : "memory");
}
__device__ __forceinline__ void st_async_u64(uint32_t raddr, u64 v, uint32_t rmbar) {
    asm volatile("st.async.shared::cluster.mbarrier::complete_tx::bytes.b64 [%0], %1, [%2];"
                 :: "r"(raddr), "l"(v), "r"(rmbar) : "memory");
}
__device__ __forceinline__ void mbar_wait_parity(uint32_t addr, uint32_t parity) {
    uint32_t done;
    asm volatile(
        "{\n\t.reg .pred p;\n\t"
        "mbarrier.try_wait.parity.acquire.cluster.shared::cta.b64 p, [%1], %2;\n\t"
        "selp.b32 %0, 1, 0, p;\n\t}"
        : "=r"(done) : "r"(addr), "r"(parity) : "memory");
    if (!done) {
        asm volatile(
            "{\n\t.reg .pred P1;\n\t"
            "WL_%=:\n\t"
            "mbarrier.try_wait.parity.acquire.cluster.shared::cta.b64 P1, [%0], %1, 0x989680;\n\t"
            "@P1 bra.uni WD_%=;\n\t"
            "bra.uni WL_%=;\n\t"
            "WD_%=:\n\t}"
            :: "r"(addr), "r"(parity) : "memory");
    }
}
__device__ __forceinline__ void named_bar(int id, int nthr) {
    asm volatile("bar.sync %0, %1;" :: "r"(id), "r"(nthr) : "memory");
}

__device__ __forceinline__ float sigm(float x)  { return __fdividef(1.f, 1.f + __expf(-x)); }
__device__ __forceinline__ float tanhf_(float x){ return __fdividef(2.f, 1.f + __expf(-2.f * x)) - 1.f; }

// ---------------------------------------------------------------------------
// Tiled GEMM: C[M,N] = A[M,K] @ B[N,K]^T + bias[N]   (unchanged, known-good)
// ---------------------------------------------------------------------------
__global__ __launch_bounds__(256)
void gemm_bias_kernel(const float* __restrict__ A, const float* __restrict__ Bm,
                      const float* __restrict__ bias, float* __restrict__ C,
                      int M, int N, int K)
{
    __shared__ __align__(16) float As[8][132];
    __shared__ __align__(16) float Bs[8][68];

    const int tx = threadIdx.x & 15;
    const int ty = threadIdx.x >> 4;
    const int m0 = blockIdx.y * 128;
    const int n0 = blockIdx.x * 64;

    u64 acc[4][4];
#pragma unroll
    for (int p = 0; p < 4; p++)
#pragma unroll
        for (int c = 0; c < 4; c++) acc[p][c] = 0ull;

    for (int k0 = 0; k0 < K; k0 += 8) {
#pragma unroll
        for (int i = 0; i < 4; i++) {
            int idx = threadIdx.x + i * 256;
            int m = idx >> 3, k = idx & 7;
            float v = 0.0f;
            if (k0 + k < K) v = A[(size_t)(m0 + m) * K + (k0 + k)];
            As[k][m] = v;
        }
#pragma unroll
        for (int i = 0; i < 2; i++) {
            int idx = threadIdx.x + i * 256;
            int n = idx >> 3, k = idx & 7;
            float v = 0.0f;
            if (k0 + k < K) v = Bm[(size_t)(n0 + n) * K + (k0 + k)];
            Bs[k][n] = v;
        }
        __syncthreads();

#pragma unroll
        for (int k = 0; k < 8; k++) {
            float4 a0 = *(const float4*)&As[k][ty * 8];
            float4 a1 = *(const float4*)&As[k][ty * 8 + 4];
            float4 b  = *(const float4*)&Bs[k][tx * 4];
            u64 ap[4] = { pack2(a0.x, a0.y), pack2(a0.z, a0.w),
                          pack2(a1.x, a1.y), pack2(a1.z, a1.w) };
            u64 bb[4] = { pack2(b.x, b.x), pack2(b.y, b.y),
                          pack2(b.z, b.z), pack2(b.w, b.w) };
#pragma unroll
            for (int p = 0; p < 4; p++)
#pragma unroll
                for (int c = 0; c < 4; c++)
                    acc[p][c] = ffma2(ap[p], bb[c], acc[p][c]);
        }
        __syncthreads();
    }

    float bv[4];
#pragma unroll
    for (int c = 0; c < 4; c++) bv[c] = bias[n0 + tx * 4 + c];

#pragma unroll
    for (int p = 0; p < 4; p++) {
        float lo[4], hi[4];
#pragma unroll
        for (int c = 0; c < 4; c++) unpack2(acc[p][c], lo[c], hi[c]);
        int r0 = m0 + ty * 8 + 2 * p;
        float4 o0 = make_float4(lo[0] + bv[0], lo[1] + bv[1], lo[2] + bv[2], lo[3] + bv[3]);
        float4 o1 = make_float4(hi[0] + bv[0], hi[1] + bv[1], hi[2] + bv[2], hi[3] + bv[3]);
        *(float4*)&C[(size_t)r0 * N + n0 + tx * 4]       = o0;
        *(float4*)&C[(size_t)(r0 + 1) * N + n0 + tx * 4] = o1;
    }
}

// ---------------------------------------------------------------------------
// Pipelined cluster GRU recurrence.
// Cluster of 4 CTAs, 8 batch rows, split into 2 independent row-groups of 4
// rows (2 row-pairs). Group g = warps 4g..4g+3 (one warp per SMSP per group).
// Thread (g, u, s): u = hidden unit within CTA's 64, s = k-slice (128 k) and
// row-pair owner. Per step per group: GEMM (768 FFMA2/thread) -> 2-slice
// reduce via smem + named bar -> activations -> st.async h row-pair to all 4
// CTAs with tx completion on per-group mbarrier -> try_wait next phase.
// Groups run phase-shifted: one group's serial tail hides under the other's
// GEMM. No cluster.sync in the loop.
// SMEM: Ws 192KB | hb u64[2g][2par][256][2p] 16KB | red u64[2g][2s][64][3] 6KB
// ---------------------------------------------------------------------------
#define WS_BYTES  196608
#define HB_OFF    WS_BYTES
#define RED_OFF   (HB_OFF + 16384)
#define MB_OFF    (RED_OFF + 6144)
#define GRU_SMEM  (MB_OFF + 128)          // 219264

template<bool WRITE_OUT, bool WRITE_HT>
__global__ void __cluster_dims__(4, 1, 1) __launch_bounds__(256, 1)
gru_cluster_kernel(const float* __restrict__ xg, const float* __restrict__ Whh,
                   const float* __restrict__ bhh,
                   float* __restrict__ out, float* __restrict__ hT)
{
    extern __shared__ __align__(16) char smem[];
    float* Ws  = (float*)smem;                  // [256 k][192 (g*64+u)]
    u64*   hb  = (u64*)(smem + HB_OFF);         // [(g*2+par)*256 + k]*2 + pair
    u64*   red = (u64*)(smem + RED_OFF);        // [(g*2+s)*64 + u]*3 + gate
    u64*   mbs = (u64*)(smem + MB_OFF);         // [2] mbarriers

    const int tid = threadIdx.x;
    const int g   = tid >> 7;                   // row-group 0/1
    const int r7  = tid & 127;
    const int u   = r7 & 63;
    const int s   = r7 >> 6;                    // k-slice / row-pair owner
    const uint32_t crank = ctarank_();
    const int cu  = (int)crank * 64 + u;
    const int row = (blockIdx.x >> 2) * 8 + g * 4 + s * 2;

    // ---- stage this CTA's 192 W_hh rows into SMEM, k-major ----
    for (int idx = tid; idx < 192 * 64; idx += 256) {
        int o  = idx % 192;
        int kb = idx / 192;
        int gg = o >> 6, uo = o & 63;
        int grow = gg * 256 + (int)crank * 64 + uo;
        float4 w = ((const float4*)Whh)[grow * 64 + kb];
        float* base = Ws + (kb * 4) * 192 + o;
        base[0] = w.x; base[192] = w.y; base[384] = w.z; base[576] = w.w;
    }
    for (int i = tid; i < 2048; i += 256) hb[i] = 0ull;
    if (tid == 0) {
        mbar_init(smem_u32(&mbs[0]), 1);
        mbar_init(smem_u32(&mbs[1]), 1);
    }
    __syncthreads();
    CLUSTER_BAR();   // W, h zeros, mbarriers visible cluster-wide

    const float br = bhh[cu], bz = bhh[256 + cu], bn = bhh[512 + cu];

    // remote addresses for this thread's h slot (parity 0) + group mbar
    uint32_t slot0  = smem_u32(&hb[(size_t)((g * 2 + 0) * 256 + cu) * 2 + s]);
    uint32_t mlocal = smem_u32(&mbs[g]);
    uint32_t haddr[4], maddr[4];
#pragma unroll
    for (int i = 0; i < 4; i++) {
        uint32_t rk = (crank + i) & 3;
        haddr[i] = mapa_(slot0, rk);
        maddr[i] = mapa_(mlocal, rk);
    }

    const float* px0 = xg + ((size_t)row * T_) * G3_ + cu;
    const float* px1 = px0 + (size_t)T_ * G3_;
    float* po0 = WRITE_OUT ? out + ((size_t)row * T_) * H_ + cu : nullptr;
    float* po1 = WRITE_OUT ? po0 + (size_t)T_ * H_ : nullptr;

    float hp0 = 0.f, hp1 = 0.f;
    const bool elected = (r7 == 0);

    for (int t = 0; t < T_; t++) {
        // xg prefetch: independent of h(t), issue before the wait
        float x_r0 = px0[0], x_z0 = px0[256], x_n0 = px0[512];
        float x_r1 = px1[0], x_z1 = px1[256], x_n1 = px1[512];

        if (t > 0) mbar_wait_parity(mlocal, (uint32_t)((t - 1) & 1));

        // GEMM: k-slice s (128 k), both row-pairs, 3 gates
        u64 a00 = 0, a01 = 0, a02 = 0;   // pair 0: r z n
        u64 a10 = 0, a11 = 0, a12 = 0;   // pair 1: r z n
        {
            const float* wsp = Ws + (size_t)(s * 128) * 192;
            const u64*   hk  = hb + (size_t)((g * 2 + (t & 1)) * 256 + s * 128) * 2;
#pragma unroll 4
            for (int k = 0; k < 128; k++) {
                float wr = wsp[u], wz = wsp[64 + u], wn = wsp[128 + u];
                ulonglong2 h2 = *(const ulonglong2*)hk;   // pair0, pair1
                u64 wr2 = pack2(wr, wr), wz2 = pack2(wz, wz), wn2 = pack2(wn, wn);
                a00 = ffma2(h2.x, wr2, a00); a10 = ffma2(h2.y, wr2, a10);
                a01 = ffma2(h2.x, wz2, a01); a11 = ffma2(h2.y, wz2, a11);
                a02 = ffma2(h2.x, wn2, a02); a12 = ffma2(h2.y, wn2, a12);
                wsp += 192; hk += 2;
            }
        }

        // store partial for the pair the partner finalizes
        u64* rslot = &red[(size_t)((g * 2 + s) * 64 + u) * 3];
        if (s == 0) { rslot[0] = a10; rslot[1] = a11; rslot[2] = a12; }
        else        { rslot[0] = a00; rslot[1] = a01; rslot[2] = a02; }
        named_bar(1 + g, 128);

        // arm next-phase completion early (strictly precedes this CTA's stores)
        if (elected && t < T_ - 1) mbar_expect_tx(mlocal, 4096);

        const u64* pslot = &red[(size_t)((g * 2 + (1 - s)) * 64 + u) * 3];
        u64 vr, vz, vn;
        if (s == 0) { vr = add2(a00, pslot[0]); vz = add2(a01, pslot[1]); vn = add2(a02, pslot[2]); }
        else        { vr = add2(a10, pslot[0]); vz = add2(a11, pslot[1]); vn = add2(a12, pslot[2]); }

        float pr0, pr1, pz0, pz1, pn0, pn1;
        unpack2(vr, pr0, pr1); unpack2(vz, pz0, pz1); unpack2(vn, pn0, pn1);

        float r0 = sigm(x_r0 + pr0 + br);
        float z0 = sigm(x_z0 + pz0 + bz);
        float n0 = tanhf_(x_n0 + r0 * (pn0 + bn));
        float h0 = n0 + z0 * (hp0 - n0);

        float r1 = sigm(x_r1 + pr1 + br);
        float z1 = sigm(x_z1 + pz1 + bz);
        float n1 = tanhf_(x_n1 + r1 * (pn1 + bn));
        float h1 = n1 + z1 * (hp1 - n1);

        if (WRITE_OUT) { po0[0] = h0; po1[0] = h1; po0 += H_; po1 += H_; }

        if (t < T_ - 1) {
            u64 hv = pack2(h0, h1);
            uint32_t poff = (uint32_t)((t + 1) & 1) * 4096u;
#pragma unroll
            for (int i = 0; i < 4; i++)
                st_async_u64(haddr[i] + poff, hv, maddr[i]);
        }

        hp0 = h0; hp1 = h1;
        px0 += G3_; px1 += G3_;
    }

    if (WRITE_HT) {
        hT[(size_t)row * H_ + cu]       = hp0;
        hT[(size_t)(row + 1) * H_ + cu] = hp1;
    }
    CLUSTER_BAR();   // no CTA exits with peers' remote accesses conceivably in flight
}

// ---------------------------------------------------------------------------
extern "C" void kernel_launch(void* const* d_in, const int* in_sizes, int n_in,
                              void* d_out, int out_size)
{
    const float* x     = (const float*)d_in[0];
    const float* W_ih0 = (const float*)d_in[1];
    const float* W_hh0 = (const float*)d_in[2];
    const float* b_ih0 = (const float*)d_in[3];
    const float* b_hh0 = (const float*)d_in[4];
    const float* W_ih1 = (const float*)d_in[5];
    const float* W_hh1 = (const float*)d_in[6];
    const float* b_ih1 = (const float*)d_in[7];
    const float* b_hh1 = (const float*)d_in[8];
    const float* fc_W  = (const float*)d_in[9];
    const float* fc_b  = (const float*)d_in[10];
    float* out = (float*)d_out;

    float *xg, *out0, *hT;
    cudaGetSymbolAddress((void**)&xg,   g_xg);
    cudaGetSymbolAddress((void**)&out0, g_out0);
    cudaGetSymbolAddress((void**)&hT,   g_hT);

    static int smem_set = 0;
    if (!smem_set) {
        cudaFuncSetAttribute(gru_cluster_kernel<true,  false>,
                             cudaFuncAttributeMaxDynamicSharedMemorySize, GRU_SMEM);
        cudaFuncSetAttribute(gru_cluster_kernel<false, true>,
                             cudaFuncAttributeMaxDynamicSharedMemorySize, GRU_SMEM);
        smem_set = 1;
    }

    const int MT = B_ * T_;

    gemm_bias_kernel<<<dim3(G3_ / 64, MT / 128), 256>>>(x, W_ih0, b_ih0, xg, MT, G3_, INDIM_);
    gru_cluster_kernel<true,  false><<<128, 256, GRU_SMEM>>>(xg, W_hh0, b_hh0, out0, nullptr);
    gemm_bias_kernel<<<dim3(G3_ / 64, MT / 128), 256>>>(out0, W_ih1, b_ih1, xg, MT, G3_, H_);
    gru_cluster_kernel<false, true><<<128, 256, GRU_SMEM>>>(xg, W_hh1, b_hh1, nullptr, hT);
    gemm_bias_kernel<<<dim3(H_ / 64, B_ / 128), 256>>>(hT, fc_W, fc_b, out, B_, H_, H_);
}